// round 7
// baseline (speedup 1.0000x reference)
#include <cuda_runtime.h>
#include <cstdint>

#define NNODES 50000
#define HID    128
#define NREL   9
#define NEDGES 600000
#define RNBUCK (NREL * NNODES)
#define CAP    32                           // bucket capacity (λ=1.33; P(>32)≈0)
#define WTOT   (3 * NREL * HID * HID)       // 442368

#define MT      128                         // M rows per block tile
#define GRID_L  ((NNODES + MT - 1) / MT)    // 391
#define THREADS 512                         // 8 producer + 8 consumer warps
#define APAD    132                         // A smem pad (A-frag conflict-free)
#define WPAD    136                         // W smem pad (B-frag conflict-free)

// ---------------- scratch (device globals; no allocation allowed) ----------
__device__ int g_counts[RNBUCK];
__device__ int g_bucket[(size_t)RNBUCK * CAP];            // 57.6 MB
__device__ __align__(256) float g_H[2][(size_t)NNODES * HID];
__device__ __align__(256) float g_Wt[WTOT];               // tf32-pre-rounded W

// ---------------- helpers --------------------------------------------------
__device__ __forceinline__ float tf32r(float x) {
    uint32_t u;
    asm("cvt.rna.tf32.f32 %0, %1;" : "=r"(u) : "f"(x));
    return __uint_as_float(u);
}
__device__ __forceinline__ void mma_tf32(float& c0, float& c1, float& c2, float& c3,
                                         uint32_t a0, uint32_t a1, uint32_t a2, uint32_t a3,
                                         uint32_t b0, uint32_t b1) {
    asm volatile(
        "mma.sync.aligned.m16n8k8.row.col.f32.tf32.tf32.f32 "
        "{%0,%1,%2,%3}, {%4,%5,%6,%7}, {%8,%9}, {%0,%1,%2,%3};\n"
        : "+f"(c0), "+f"(c1), "+f"(c2), "+f"(c3)
        : "r"(a0), "r"(a1), "r"(a2), "r"(a3), "r"(b0), "r"(b1));
}
__device__ __forceinline__ void bar_sync(int id, int cnt) {
    asm volatile("bar.sync %0, %1;" :: "r"(id), "r"(cnt) : "memory");
}
__device__ __forceinline__ void bar_arrive(int id, int cnt) {
    asm volatile("bar.arrive %0, %1;" :: "r"(id), "r"(cnt) : "memory");
}

// ---------------- init: zero counts + tf32-round W --------------------------
__global__ void k_init(const float* __restrict__ W) {
    int i = blockIdx.x * blockDim.x + threadIdx.x;
    if (i < WTOT)   g_Wt[i] = tf32r(W[i]);
    if (i < RNBUCK) g_counts[i] = 0;
}

// ---------------- bucket scatter: one pass, no sort -------------------------
__global__ void k_bucket(const int* __restrict__ dest, const int* __restrict__ etype,
                         const int* __restrict__ src) {
    int e = blockIdx.x * blockDim.x + threadIdx.x;
    if (e < NEDGES) {
        int key = etype[e] * NNODES + dest[e];
        int pos = atomicAdd(&g_counts[key], 1);
        if (pos < CAP) g_bucket[(size_t)key * CAP + pos] = src[e];
    }
}

// ---------------- fused layer kernel: warp-specialized ----------------------
// 512 threads. Warps 0-7 = producers: gather-sum H[src] rows of relation r into
// double-buffered smem A[b] (tf32-rounded). Warps 8-15 = consumers: per
// relation load W[l,r] into smem, then C += A[b] @ W with mma.sync tf32.
// Named barriers: full[b]=3+b (prod arrive / cons sync), empty[b]=1+b
// (cons arrive / prod sync), 5 = consumer-only (W buffer reuse + visibility).
struct SMem {
    float A[2][MT * APAD];       // 2 x 67.6 KB
    float W[HID * WPAD];         // 69.6 KB
    float bias[NREL * HID];      // 4.5 KB
};

__global__ void __launch_bounds__(THREADS, 1)
k_layer(const float* __restrict__ Hin, const float* __restrict__ Wt_l,
        const float* __restrict__ Bv, float* __restrict__ Hout, int relu) {
    extern __shared__ __align__(16) char smraw[];
    SMem* sm = (SMem*)smraw;

    const int tid  = threadIdx.x;
    const int lane = tid & 31;
    const int wid  = tid >> 5;
    const int base = blockIdx.x * MT;

    for (int i = tid; i < NREL * HID; i += THREADS) sm->bias[i] = Bv[i];
    __syncthreads();

    if (wid < 8) {
        // ================= PRODUCER =================
        const int rowbase = wid * 16;              // 16 rows per warp
        const int mycol   = lane * 4;
        const int d0      = base + rowbase;

        for (int r = 0; r < NREL; r++) {
            const int b = r & 1;
            if (r >= 2) bar_sync(1 + b, 512);      // wait A[b] empty
            float* Ab = sm->A[b];

            // per-row counts (clamped to CAP) + warp exclusive scan
            int cnt = 0;
            {
                int dd = d0 + lane;
                if (lane < 16 && dd < NNODES) {
                    cnt = g_counts[r * NNODES + dd];
                    if (cnt > CAP) cnt = CAP;
                }
            }
            int x = cnt;
            #pragma unroll
            for (int o = 1; o < 32; o <<= 1) {
                int y = __shfl_up_sync(0xffffffffu, x, o);
                if (lane >= o) x += y;
            }
            const int excl  = x - cnt;             // lane j: excl prefix; lane16 = total
            const int total = __shfl_sync(0xffffffffu, excl, 16);

            float4 acc = make_float4(0.f, 0.f, 0.f, 0.f);
            int cur = 0;
            int nextb = __shfl_sync(0xffffffffu, excl, 1);

            #define FLUSH() do { \
                float4 o_; o_.x = tf32r(acc.x); o_.y = tf32r(acc.y); \
                o_.z = tf32r(acc.z); o_.w = tf32r(acc.w); \
                *(float4*)(Ab + (rowbase + cur) * APAD + mycol) = o_; \
                acc.x = acc.y = acc.z = acc.w = 0.f; \
                cur++; \
                int nb2 = __shfl_sync(0xffffffffu, excl, (cur < 16) ? (cur + 1) : 16); \
                nextb = (cur < 16) ? nb2 : 0x7fffffff; \
            } while (0)

            for (int ib = 0; ib < total; ib += 32) {
                int rem = total - ib; if (rem > 32) rem = 32;
                const int j = ib + lane;

                // locate (row, slot) for edge j: row = max{i: excl_i <= j}
                int row = -1;
                #pragma unroll
                for (int i = 0; i < 16; i++) {
                    int p = __shfl_sync(0xffffffffu, excl, i);
                    row += (p <= j) ? 1 : 0;
                }
                if (row < 0) row = 0;
                if (row > 15) row = 15;
                int rowExcl = __shfl_sync(0xffffffffu, excl, row);
                int slot = j - rowExcl;
                if (slot < 0) slot = 0;
                if (slot >= CAP) slot = CAP - 1;

                int sv = 0;
                if (lane < rem)
                    sv = g_bucket[(size_t)(r * NNODES + d0 + row) * CAP + slot];

                int jj = 0;
                while (jj < rem) {
                    int nb = rem - jj; if (nb > 8) nb = 8;
                    float4 v[8];
                    #pragma unroll
                    for (int u = 0; u < 8; u++) {
                        if (u < nb) {
                            int s = __shfl_sync(0xffffffffu, sv, jj + u);
                            v[u] = *(const float4*)(Hin + (size_t)s * HID + mycol);
                        }
                    }
                    #pragma unroll
                    for (int u = 0; u < 8; u++) {
                        if (u < nb) {
                            int idx = ib + jj + u;
                            while (idx >= nextb) FLUSH();
                            acc.x += v[u].x; acc.y += v[u].y;
                            acc.z += v[u].z; acc.w += v[u].w;
                        }
                    }
                    jj += nb;
                }
            }
            while (cur < 16) FLUSH();
            #undef FLUSH

            bar_arrive(3 + b, 512);                // signal A[b] full
        }
    } else {
        // ================= CONSUMER =================
        const int cw = wid - 8;
        const int wm = cw & 3;                     // M group: rows [wm*32, +32)
        const int wncol = (cw >> 2) * 64;          // N group: cols [wncol, +64)
        const int g  = lane >> 2;
        const int tg = lane & 3;
        const int ctid = tid - 256;                // 0..255

        float c[2][8][4];
        #pragma unroll
        for (int m2 = 0; m2 < 2; m2++)
            #pragma unroll
            for (int nt = 0; nt < 8; nt++)
                #pragma unroll
                for (int j = 0; j < 4; j++) c[m2][nt][j] = 0.0f;

        for (int r = 0; r < NREL; r++) {
            const int b = r & 1;

            if (r > 0) bar_sync(5, 256);           // all consumers done with W
            {   // load pre-rounded W[l,r] into smem
                const float4* src = (const float4*)(Wt_l + (size_t)r * (HID * HID));
                #pragma unroll
                for (int i = ctid; i < (HID * HID) / 4; i += 256) {
                    float4 v = src[i];
                    int idx = i * 4;
                    *(float4*)(sm->W + (idx >> 7) * WPAD + (idx & 127)) = v;
                }
            }
            bar_sync(5, 256);                      // W visible to all consumers
            bar_sync(3 + b, 512);                  // wait A[b] full

            const float* Ab = sm->A[b];
            #pragma unroll 4
            for (int kk = 0; kk < HID; kk += 8) {
                const int a00 = (wm * 32 + g) * APAD + kk + tg;
                const int a10 = (wm * 32 + 16 + g) * APAD + kk + tg;
                uint32_t a0[2], a1[2], a2[2], a3[2];
                a0[0] = __float_as_uint(Ab[a00]);
                a1[0] = __float_as_uint(Ab[a00 + 8 * APAD]);
                a2[0] = __float_as_uint(Ab[a00 + 4]);
                a3[0] = __float_as_uint(Ab[a00 + 8 * APAD + 4]);
                a0[1] = __float_as_uint(Ab[a10]);
                a1[1] = __float_as_uint(Ab[a10 + 8 * APAD]);
                a2[1] = __float_as_uint(Ab[a10 + 4]);
                a3[1] = __float_as_uint(Ab[a10 + 8 * APAD + 4]);
                #pragma unroll
                for (int nt = 0; nt < 8; nt++) {
                    const int ncol = wncol + nt * 8 + g;
                    uint32_t b0 = __float_as_uint(sm->W[(kk + tg) * WPAD + ncol]);
                    uint32_t b1 = __float_as_uint(sm->W[(kk + tg + 4) * WPAD + ncol]);
                    mma_tf32(c[0][nt][0], c[0][nt][1], c[0][nt][2], c[0][nt][3],
                             a0[0], a1[0], a2[0], a3[0], b0, b1);
                    mma_tf32(c[1][nt][0], c[1][nt][1], c[1][nt][2], c[1][nt][3],
                             a0[1], a1[1], a2[1], a3[1], b0, b1);
                }
            }
            bar_arrive(1 + b, 512);                // signal A[b] empty
        }

        // ---- epilogue: bias via per-row true counts, relu, store ----
        #pragma unroll
        for (int m2 = 0; m2 < 2; m2++) {
            #pragma unroll
            for (int h = 0; h < 2; h++) {
                const int row = wm * 32 + m2 * 16 + h * 8 + g;
                const int d = base + row;
                if (d >= NNODES) continue;
                float cnt[NREL];
                #pragma unroll
                for (int r = 0; r < NREL; r++)
                    cnt[r] = (float)g_counts[r * NNODES + d];
                #pragma unroll
                for (int nt = 0; nt < 8; nt++) {
                    const int col0 = wncol + nt * 8 + tg * 2;
                    float v0 = c[m2][nt][h * 2 + 0];
                    float v1 = c[m2][nt][h * 2 + 1];
                    #pragma unroll
                    for (int r = 0; r < NREL; r++) {
                        const float cc = cnt[r];
                        v0 += cc * sm->bias[r * HID + col0];
                        v1 += cc * sm->bias[r * HID + col0 + 1];
                    }
                    if (relu) { v0 = fmaxf(v0, 0.f); v1 = fmaxf(v1, 0.f); }
                    Hout[(size_t)d * HID + col0]     = v0;
                    Hout[(size_t)d * HID + col0 + 1] = v1;
                }
            }
        }
    }
}

// ---------------- launch ----------------------------------------------------
extern "C" void kernel_launch(void* const* d_in, const int* in_sizes, int n_in,
                              void* d_out, int out_size) {
    const int*   eidx  = (const int*)d_in[0];      // [2, NEDGES]: row0=dest, row1=src
    const int*   etype = (const int*)d_in[1];
    const float* emb   = (const float*)d_in[2];
    const float* wts   = (const float*)d_in[3];    // [3, NREL, HID, HID]
    const float* bias  = (const float*)d_in[4];    // [3, NREL, HID]
    float*       out   = (float*)d_out;

    const int* dest = eidx;
    const int* src  = eidx + NEDGES;

    float* hbuf = nullptr;
    cudaGetSymbolAddress((void**)&hbuf, g_H);
    float* H0 = hbuf;
    float* H1 = hbuf + (size_t)NNODES * HID;
    float* wt = nullptr;
    cudaGetSymbolAddress((void**)&wt, g_Wt);

    // bucket build: 2 launches total
    k_init<<<(RNBUCK + 255) / 256, 256>>>(wts);
    k_bucket<<<(NEDGES + 255) / 256, 256>>>(dest, etype, src);

    const int smem_sz = (int)sizeof(SMem);
    static_assert(sizeof(SMem) <= 227 * 1024, "smem too big");
    cudaFuncSetAttribute(k_layer, cudaFuncAttributeMaxDynamicSharedMemorySize, smem_sz);

    const size_t wstride = (size_t)NREL * HID * HID;
    const size_t bstride = (size_t)NREL * HID;

    k_layer<<<GRID_L, THREADS, smem_sz>>>(emb, wt,               bias,               H0,  1);
    k_layer<<<GRID_L, THREADS, smem_sz>>>(H0,  wt + wstride,     bias + bstride,     H1,  1);
    k_layer<<<GRID_L, THREADS, smem_sz>>>(H1,  wt + 2 * wstride, bias + 2 * bstride, out, 0);
}

// round 8
// speedup vs baseline: 1.3696x; 1.3696x over previous
#include <cuda_runtime.h>
#include <cstdint>

#define NNODES  50000
#define HID     128
#define NREL    9
#define NEDGES  600000
#define RNBUCK  (NREL * NNODES)
#define CAP     32
#define WTOT    (3 * NREL * HID * HID)

#define MTILE   128
#define NROWPAD 50048                          // 391 * 128
#define GRID_M  (NROWPAD / MTILE)              // 391

#define NSTAGE  3
#define APAD_G  36                             // A smem row pitch (floats)
#define WPAD_G  132                            // W smem row pitch (floats)
#define AS_ELE  (MTILE * APAD_G)               // 4608
#define WS_ELE  (32 * WPAD_G)                  // 4224
#define NSLICE  (NREL * 4)                     // 36 K-slices of 32

// ---------------- scratch (device globals; no allocation) ----------------
__device__ int   g_counts[RNBUCK];
__device__ int   g_bucket[(size_t)RNBUCK * CAP];                  // 57.6 MB
__device__ __align__(256) float g_H[2][(size_t)NNODES * HID];
__device__ __align__(256) float g_Wt[WTOT];                       // tf32-rounded W
__device__ __align__(256) float g_Y[(size_t)NREL * NROWPAD * HID]; // 230.6 MB

// ---------------- helpers ----------------
__device__ __forceinline__ float tf32r(float x) {
    uint32_t u;
    asm("cvt.rna.tf32.f32 %0, %1;" : "=r"(u) : "f"(x));
    return __uint_as_float(u);
}
__device__ __forceinline__ void mma_tf32(float& c0, float& c1, float& c2, float& c3,
                                         uint32_t a0, uint32_t a1, uint32_t a2, uint32_t a3,
                                         uint32_t b0, uint32_t b1) {
    asm volatile(
        "mma.sync.aligned.m16n8k8.row.col.f32.tf32.tf32.f32 "
        "{%0,%1,%2,%3}, {%4,%5,%6,%7}, {%8,%9}, {%0,%1,%2,%3};\n"
        : "+f"(c0), "+f"(c1), "+f"(c2), "+f"(c3)
        : "r"(a0), "r"(a1), "r"(a2), "r"(a3), "r"(b0), "r"(b1));
}
__device__ __forceinline__ void cp16(uint32_t sdst, const void* gsrc) {
    asm volatile("cp.async.cg.shared.global [%0], [%1], 16;\n"
                 :: "r"(sdst), "l"(gsrc) : "memory");
}
__device__ __forceinline__ void cp_commit() {
    asm volatile("cp.async.commit_group;\n" ::: "memory");
}
__device__ __forceinline__ void cp_wait2() {
    asm volatile("cp.async.wait_group 2;\n" ::: "memory");
}

// ---------------- init: zero counts + tf32-round W ----------------
__global__ void k_init(const float* __restrict__ W) {
    int i = blockIdx.x * blockDim.x + threadIdx.x;
    if (i < WTOT)   g_Wt[i] = tf32r(W[i]);
    if (i < RNBUCK) g_counts[i] = 0;
}

// ---------------- bucket scatter ----------------
__global__ void k_bucket(const int* __restrict__ dest, const int* __restrict__ etype,
                         const int* __restrict__ src) {
    int e = blockIdx.x * blockDim.x + threadIdx.x;
    if (e < NEDGES) {
        int key = etype[e] * NNODES + dest[e];
        int pos = atomicAdd(&g_counts[key], 1);
        if (pos < CAP) g_bucket[(size_t)key * CAP + pos] = src[e];
    }
}

// ---------------- gather: Y[r][n][:] = sum_{src in bucket(r,n)} Hin[src] ----
// grid (391, 9), 256 threads. Each warp owns 16 dest rows of relation
// blockIdx.y. Rows >= NNODES (and empty buckets) are written as zeros.
__global__ void __launch_bounds__(256)
k_gather(const float* __restrict__ Hin) {
    const int lane = threadIdx.x & 31;
    const int wid  = threadIdx.x >> 5;
    const int r    = blockIdx.y;
    const int d0   = blockIdx.x * MTILE + wid * 16;
    const int mycol = lane * 4;
    float* Yg = g_Y + (size_t)r * NROWPAD * HID;

    // per-row counts (clamped) + warp exclusive scan
    int cnt = 0;
    {
        int dd = d0 + lane;
        if (lane < 16 && dd < NNODES) {
            cnt = g_counts[r * NNODES + dd];
            if (cnt > CAP) cnt = CAP;
        }
    }
    int x = cnt;
    #pragma unroll
    for (int o = 1; o < 32; o <<= 1) {
        int y = __shfl_up_sync(0xffffffffu, x, o);
        if (lane >= o) x += y;
    }
    const int excl  = x - cnt;
    const int total = __shfl_sync(0xffffffffu, excl, 16);

    float4 acc = make_float4(0.f, 0.f, 0.f, 0.f);
    int cur = 0;
    int nextb = __shfl_sync(0xffffffffu, excl, 1);

    #define FLUSH() do { \
        float4 o_; o_.x = tf32r(acc.x); o_.y = tf32r(acc.y); \
        o_.z = tf32r(acc.z); o_.w = tf32r(acc.w); \
        __stcs((float4*)(Yg + (size_t)(d0 + cur) * HID + mycol), o_); \
        acc.x = acc.y = acc.z = acc.w = 0.f; \
        cur++; \
        int nb2 = __shfl_sync(0xffffffffu, excl, (cur < 16) ? (cur + 1) : 16); \
        nextb = (cur < 16) ? nb2 : 0x7fffffff; \
    } while (0)

    for (int ib = 0; ib < total; ib += 32) {
        int rem = total - ib; if (rem > 32) rem = 32;
        const int j = ib + lane;

        int row = -1;
        #pragma unroll
        for (int i = 0; i < 16; i++) {
            int p = __shfl_sync(0xffffffffu, excl, i);
            row += (p <= j) ? 1 : 0;
        }
        if (row < 0) row = 0;
        if (row > 15) row = 15;
        int rowExcl = __shfl_sync(0xffffffffu, excl, row);
        int slot = j - rowExcl;
        if (slot < 0) slot = 0;
        if (slot >= CAP) slot = CAP - 1;

        int sv = 0;
        if (lane < rem)
            sv = g_bucket[(size_t)(r * NNODES + d0 + row) * CAP + slot];

        int jj = 0;
        while (jj < rem) {
            int nb = rem - jj; if (nb > 8) nb = 8;
            float4 v[8];
            #pragma unroll
            for (int u = 0; u < 8; u++) {
                if (u < nb) {
                    int s = __shfl_sync(0xffffffffu, sv, jj + u);
                    v[u] = *(const float4*)(Hin + (size_t)s * HID + mycol);
                }
            }
            #pragma unroll
            for (int u = 0; u < 8; u++) {
                if (u < nb) {
                    int idx = ib + jj + u;
                    while (idx >= nextb) FLUSH();
                    acc.x += v[u].x; acc.y += v[u].y;
                    acc.z += v[u].z; acc.w += v[u].w;
                }
            }
            jj += nb;
        }
    }
    while (cur < 16) FLUSH();
    #undef FLUSH
}

// ---------------- GEMM: Hout = relu( sum_r Y_r @ W_r + cnt_r * b_r ) --------
// 3-stage cp.async pipeline, 256 threads, tile M=128 N=128, K-slices of 32.
struct GSMem {
    float A[NSTAGE][AS_ELE];     // 54 KB
    float W[NSTAGE][WS_ELE];     // 49.5 KB
    float bias[NREL * HID];      // 4.5 KB
};

__global__ void __launch_bounds__(256, 2)
k_gemm(const float* __restrict__ Y, const float* __restrict__ Wt_l,
       const float* __restrict__ Bv, float* __restrict__ Hout, int relu) {
    extern __shared__ __align__(16) char smraw[];
    GSMem* sm = (GSMem*)smraw;

    const int tid  = threadIdx.x;
    const int lane = tid & 31;
    const int wid  = tid >> 5;
    const int base = blockIdx.x * MTILE;

    for (int i = tid; i < NREL * HID; i += 256) sm->bias[i] = Bv[i];

    const uint32_t sA0 = (uint32_t)__cvta_generic_to_shared(&sm->A[0][0]);
    const uint32_t sW0 = (uint32_t)__cvta_generic_to_shared(&sm->W[0][0]);

    // issue K-slice s into stage st
    #define ISSUE(s_, st_) do { \
        const int r_  = (s_) >> 2; \
        const int ks_ = (s_) & 3; \
        const float* Ag = Y + ((size_t)r_ * NROWPAD + base) * HID + ks_ * 32; \
        const float* Wg = Wt_l + ((size_t)r_ * HID + ks_ * 32) * HID; \
        const uint32_t sa = sA0 + (st_) * (AS_ELE * 4); \
        const uint32_t sw = sW0 + (st_) * (WS_ELE * 4); \
        _Pragma("unroll") \
        for (int u = 0; u < 4; u++) { \
            int j = tid + 256 * u; \
            int row = j >> 3, seg = j & 7; \
            cp16(sa + (row * APAD_G + seg * 4) * 4, Ag + (size_t)row * HID + seg * 4); \
        } \
        _Pragma("unroll") \
        for (int u = 0; u < 4; u++) { \
            int j = tid + 256 * u; \
            int row = j >> 5, c4 = (j & 31) * 4; \
            cp16(sw + (row * WPAD_G + c4) * 4, Wg + (size_t)row * HID + c4); \
        } \
        cp_commit(); \
    } while (0)

    ISSUE(0, 0); ISSUE(1, 1); ISSUE(2, 2);

    const int wm    = wid & 3;            // rows [wm*32, +32)
    const int wncol = (wid >> 2) * 64;    // cols [wncol, +64)
    const int g  = lane >> 2;
    const int tg = lane & 3;

    float c[2][8][4];
    #pragma unroll
    for (int m2 = 0; m2 < 2; m2++)
        #pragma unroll
        for (int nt = 0; nt < 8; nt++)
            #pragma unroll
            for (int j = 0; j < 4; j++) c[m2][nt][j] = 0.0f;

    for (int s = 0; s < NSLICE; s++) {
        const int st = s % NSTAGE;
        cp_wait2();
        __syncthreads();

        const float* As = sm->A[st];
        const float* Ws = sm->W[st];
        #pragma unroll
        for (int kk = 0; kk < 32; kk += 8) {
            const int a00 = (wm * 32 + g) * APAD_G + kk + tg;
            const int a10 = (wm * 32 + 16 + g) * APAD_G + kk + tg;
            uint32_t a0[2], a1[2], a2[2], a3[2];
            a0[0] = __float_as_uint(As[a00]);
            a1[0] = __float_as_uint(As[a00 + 8 * APAD_G]);
            a2[0] = __float_as_uint(As[a00 + 4]);
            a3[0] = __float_as_uint(As[a00 + 8 * APAD_G + 4]);
            a0[1] = __float_as_uint(As[a10]);
            a1[1] = __float_as_uint(As[a10 + 8 * APAD_G]);
            a2[1] = __float_as_uint(As[a10 + 4]);
            a3[1] = __float_as_uint(As[a10 + 8 * APAD_G + 4]);
            #pragma unroll
            for (int nt = 0; nt < 8; nt++) {
                const int ncol = wncol + nt * 8 + g;
                uint32_t b0 = __float_as_uint(Ws[(kk + tg) * WPAD_G + ncol]);
                uint32_t b1 = __float_as_uint(Ws[(kk + tg + 4) * WPAD_G + ncol]);
                mma_tf32(c[0][nt][0], c[0][nt][1], c[0][nt][2], c[0][nt][3],
                         a0[0], a1[0], a2[0], a3[0], b0, b1);
                mma_tf32(c[1][nt][0], c[1][nt][1], c[1][nt][2], c[1][nt][3],
                         a0[1], a1[1], a2[1], a3[1], b0, b1);
            }
        }
        __syncthreads();
        if (s + NSTAGE < NSLICE) ISSUE(s + NSTAGE, st);
    }
    #undef ISSUE

    // ---- epilogue: bias via per-row true counts, relu, store ----
    #pragma unroll
    for (int m2 = 0; m2 < 2; m2++) {
        #pragma unroll
        for (int h = 0; h < 2; h++) {
            const int row = wm * 32 + m2 * 16 + h * 8 + g;
            const int d = base + row;
            if (d >= NNODES) continue;
            float cnt[NREL];
            #pragma unroll
            for (int r = 0; r < NREL; r++)
                cnt[r] = (float)g_counts[r * NNODES + d];
            #pragma unroll
            for (int nt = 0; nt < 8; nt++) {
                const int col0 = wncol + nt * 8 + tg * 2;
                float v0 = c[m2][nt][h * 2 + 0];
                float v1 = c[m2][nt][h * 2 + 1];
                #pragma unroll
                for (int r = 0; r < NREL; r++) {
                    const float cc = cnt[r];
                    v0 += cc * sm->bias[r * HID + col0];
                    v1 += cc * sm->bias[r * HID + col0 + 1];
                }
                if (relu) { v0 = fmaxf(v0, 0.f); v1 = fmaxf(v1, 0.f); }
                Hout[(size_t)d * HID + col0]     = v0;
                Hout[(size_t)d * HID + col0 + 1] = v1;
            }
        }
    }
}

// ---------------- launch ----------------------------------------------------
extern "C" void kernel_launch(void* const* d_in, const int* in_sizes, int n_in,
                              void* d_out, int out_size) {
    const int*   eidx  = (const int*)d_in[0];      // [2, NEDGES]: row0=dest, row1=src
    const int*   etype = (const int*)d_in[1];
    const float* emb   = (const float*)d_in[2];
    const float* wts   = (const float*)d_in[3];    // [3, NREL, HID, HID]
    const float* bias  = (const float*)d_in[4];    // [3, NREL, HID]
    float*       out   = (float*)d_out;

    const int* dest = eidx;
    const int* src  = eidx + NEDGES;

    float* hbuf = nullptr;
    cudaGetSymbolAddress((void**)&hbuf, g_H);
    float* H0 = hbuf;
    float* H1 = hbuf + (size_t)NNODES * HID;
    float* wt = nullptr;
    cudaGetSymbolAddress((void**)&wt, g_Wt);
    float* yb = nullptr;
    cudaGetSymbolAddress((void**)&yb, g_Y);

    k_init<<<(RNBUCK + 255) / 256, 256>>>(wts);
    k_bucket<<<(NEDGES + 255) / 256, 256>>>(dest, etype, src);

    const int smem_sz = (int)sizeof(GSMem);
    static_assert(sizeof(GSMem) <= 113 * 1024, "gemm smem too big for 2 blocks/SM");
    cudaFuncSetAttribute(k_gemm, cudaFuncAttributeMaxDynamicSharedMemorySize, smem_sz);

    const size_t wstride = (size_t)NREL * HID * HID;
    const size_t bstride = (size_t)NREL * HID;
    dim3 ggrid(GRID_M, NREL);

    k_gather<<<ggrid, 256>>>(emb);
    k_gemm<<<GRID_M, 256, smem_sz>>>(yb, wt,               bias,               H0,  1);
    k_gather<<<ggrid, 256>>>(H0);
    k_gemm<<<GRID_M, 256, smem_sz>>>(yb, wt + wstride,     bias + bstride,     H1,  1);
    k_gather<<<ggrid, 256>>>(H1);
    k_gemm<<<GRID_M, 256, smem_sz>>>(yb, wt + 2 * wstride, bias + 2 * bstride, out, 0);
}

// round 12
// speedup vs baseline: 1.9105x; 1.3950x over previous
#include <cuda_runtime.h>
#include <cuda_fp16.h>
#include <cstdint>

#define NNODES  50000
#define HID     128
#define NREL    9
#define NEDGES  600000
#define RNBUCK  (NREL * NNODES)
#define CAP     32
#define WTOT    (3 * NREL * HID * HID)
#define INITN   ((RNBUCK > WTOT) ? RNBUCK : WTOT)   // cover BOTH ranges

#define MTILE   128
#define NROWPAD 50048                          // 391 * 128
#define GRID_M  (NROWPAD / MTILE)              // 391

#define NSTAGE  5
#define KSLICE  32
#define PIT     40                             // smem row pitch in halves (conflict-free)
#define AS_ELE  (MTILE * PIT)                  // 5120 halves = 10240 B
#define NSLICE  (NREL * 4)                     // 36 K-slices of 32

// ---------------- scratch (device globals; no allocation) ----------------
__device__ int    g_counts[RNBUCK];
__device__ int    g_bucket[(size_t)RNBUCK * CAP];                  // 57.6 MB
__device__ __align__(256) float  g_H[2][(size_t)NNODES * HID];
__device__ __align__(256) __half g_Wh[WTOT];                       // W^T fp16: [l][r][n][k]
__device__ __align__(256) __half g_Y[(size_t)NREL * NROWPAD * HID]; // 115 MB fp16

// ---------------- helpers ----------------
__device__ __forceinline__ void mma_f16(float& c0, float& c1, float& c2, float& c3,
                                        uint32_t a0, uint32_t a1, uint32_t a2, uint32_t a3,
                                        uint32_t b0, uint32_t b1) {
    asm volatile(
        "mma.sync.aligned.m16n8k16.row.col.f32.f16.f16.f32 "
        "{%0,%1,%2,%3}, {%4,%5,%6,%7}, {%8,%9}, {%0,%1,%2,%3};\n"
        : "+f"(c0), "+f"(c1), "+f"(c2), "+f"(c3)
        : "r"(a0), "r"(a1), "r"(a2), "r"(a3), "r"(b0), "r"(b1));
}
__device__ __forceinline__ void cp16(uint32_t sdst, const void* gsrc) {
    asm volatile("cp.async.cg.shared.global [%0], [%1], 16;\n"
                 :: "r"(sdst), "l"(gsrc) : "memory");
}
__device__ __forceinline__ void cp_commit() {
    asm volatile("cp.async.commit_group;\n" ::: "memory");
}
__device__ __forceinline__ void cp_wait() {      // NSTAGE-1 = 4
    asm volatile("cp.async.wait_group 4;\n" ::: "memory");
}

// ---------------- init: zero counts + fp16-transpose W ----------------
// g_Wh[(l*9+r)*16384 + n*128 + k] = (half) W[(l*9+r)*16384 + k*128 + n]
__global__ void k_init(const float* __restrict__ W) {
    int i = blockIdx.x * blockDim.x + threadIdx.x;
    if (i < WTOT) {
        int mat = i >> 14, within = i & 16383;
        int n = within >> 7, k = within & 127;
        g_Wh[i] = __float2half_rn(W[(mat << 14) + k * HID + n]);
    }
    if (i < RNBUCK) g_counts[i] = 0;
}

// ---------------- bucket scatter ----------------
__global__ void k_bucket(const int* __restrict__ dest, const int* __restrict__ etype,
                         const int* __restrict__ src) {
    int e = blockIdx.x * blockDim.x + threadIdx.x;
    if (e < NEDGES) {
        int key = etype[e] * NNODES + dest[e];
        int pos = atomicAdd(&g_counts[key], 1);
        if (pos < CAP) g_bucket[(size_t)key * CAP + pos] = src[e];
    }
}

// ---------------- gather: Y[r][n][:] = (half)( inv_s * sum_{src} Hin[src] ) -
// grid (391, 9), 256 threads. Each warp owns 16 dest rows of one relation.
// inv_s is a power of two chosen per layer so the fp16 store cannot overflow;
// the matching scale is re-applied in the GEMM epilogue (exact in fp).
__global__ void __launch_bounds__(256)
k_gather(const float* __restrict__ Hin, float inv_s) {
    const int lane = threadIdx.x & 31;
    const int wid  = threadIdx.x >> 5;
    const int r    = blockIdx.y;
    const int d0   = blockIdx.x * MTILE + wid * 16;
    const int mycol = lane * 4;                   // halves/floats index
    __half* Yg = g_Y + (size_t)r * NROWPAD * HID;

    int cnt = 0;
    {
        int dd = d0 + lane;
        if (lane < 16 && dd < NNODES) {
            cnt = g_counts[r * NNODES + dd];
            if (cnt > CAP) cnt = CAP;
        }
    }
    int x = cnt;
    #pragma unroll
    for (int o = 1; o < 32; o <<= 1) {
        int y = __shfl_up_sync(0xffffffffu, x, o);
        if (lane >= o) x += y;
    }
    const int excl  = x - cnt;
    const int total = __shfl_sync(0xffffffffu, excl, 16);

    float4 acc = make_float4(0.f, 0.f, 0.f, 0.f);
    int cur = 0;
    int nextb = __shfl_sync(0xffffffffu, excl, 1);

    #define FLUSH() do { \
        __half2 h0 = __floats2half2_rn(acc.x * inv_s, acc.y * inv_s); \
        __half2 h1 = __floats2half2_rn(acc.z * inv_s, acc.w * inv_s); \
        uint2 o_; o_.x = *(uint32_t*)&h0; o_.y = *(uint32_t*)&h1; \
        __stcs((uint2*)(Yg + (size_t)(d0 + cur) * HID + mycol), o_); \
        acc.x = acc.y = acc.z = acc.w = 0.f; \
        cur++; \
        int nb2 = __shfl_sync(0xffffffffu, excl, (cur < 16) ? (cur + 1) : 16); \
        nextb = (cur < 16) ? nb2 : 0x7fffffff; \
    } while (0)

    for (int ib = 0; ib < total; ib += 32) {
        int rem = total - ib; if (rem > 32) rem = 32;
        const int j = ib + lane;

        int row = -1;
        #pragma unroll
        for (int i = 0; i < 16; i++) {
            int p = __shfl_sync(0xffffffffu, excl, i);
            row += (p <= j) ? 1 : 0;
        }
        if (row < 0) row = 0;
        if (row > 15) row = 15;
        int rowExcl = __shfl_sync(0xffffffffu, excl, row);
        int slot = j - rowExcl;
        if (slot < 0) slot = 0;
        if (slot >= CAP) slot = CAP - 1;

        int sv = 0;
        if (lane < rem)
            sv = g_bucket[(size_t)(r * NNODES + d0 + row) * CAP + slot];

        int jj = 0;
        while (jj < rem) {
            int nb = rem - jj; if (nb > 8) nb = 8;
            float4 v[8];
            #pragma unroll
            for (int u = 0; u < 8; u++) {
                if (u < nb) {
                    int s = __shfl_sync(0xffffffffu, sv, jj + u);
                    v[u] = *(const float4*)(Hin + (size_t)s * HID + mycol);
                }
            }
            #pragma unroll
            for (int u = 0; u < 8; u++) {
                if (u < nb) {
                    int idx = ib + jj + u;
                    while (idx >= nextb) FLUSH();
                    acc.x += v[u].x; acc.y += v[u].y;
                    acc.z += v[u].z; acc.w += v[u].w;
                }
            }
            jj += nb;
        }
    }
    while (cur < 16) FLUSH();
    #undef FLUSH
}

// ---------------- GEMM: Hout = relu( s * sum_r Y_r @ W_r + cnt_r * b_r ) ----
// fp16 m16n8k16, fp32 accum. 5-stage cp.async pipeline, 256 thr, 128x128 tile.
struct GSMem {
    __half A[NSTAGE][AS_ELE];    // 5 x 10 KB   [row 0..127][k 0..31] pitch 40
    __half W[NSTAGE][AS_ELE];    // 5 x 10 KB   [n 0..127][k 0..31]  pitch 40
    float bias[NREL * HID];      // 4.5 KB
};

__global__ void __launch_bounds__(256, 2)
k_gemm(const __half* __restrict__ Y, const __half* __restrict__ Wt_l,
       const float* __restrict__ Bv, float* __restrict__ Hout, int relu,
       float scale) {
    extern __shared__ __align__(16) char smraw[];
    GSMem* sm = (GSMem*)smraw;

    const int tid  = threadIdx.x;
    const int lane = tid & 31;
    const int wid  = tid >> 5;
    const int base = blockIdx.x * MTILE;

    for (int i = tid; i < NREL * HID; i += 256) sm->bias[i] = Bv[i];

    const uint32_t sA0 = (uint32_t)__cvta_generic_to_shared(&sm->A[0][0]);
    const uint32_t sW0 = (uint32_t)__cvta_generic_to_shared(&sm->W[0][0]);

    // issue K-slice s into stage st: A rows + W^T rows, 32 halves each (64B = 4 cp16)
    #define ISSUE(s_, st_) do { \
        const int r_  = (s_) >> 2; \
        const int ks_ = (s_) & 3; \
        const __half* Ag = Y + ((size_t)r_ * NROWPAD + base) * HID + ks_ * KSLICE; \
        const __half* Wg = Wt_l + ((size_t)r_ << 14) + ks_ * KSLICE; \
        const uint32_t sa = sA0 + (st_) * (AS_ELE * 2); \
        const uint32_t sw = sW0 + (st_) * (AS_ELE * 2); \
        _Pragma("unroll") \
        for (int u = 0; u < 2; u++) { \
            int j = tid + 256 * u; \
            int row = j >> 2, seg = j & 3; \
            cp16(sa + (row * PIT + seg * 8) * 2, Ag + (size_t)row * HID + seg * 8); \
            cp16(sw + (row * PIT + seg * 8) * 2, Wg + (size_t)row * HID + seg * 8); \
        } \
        cp_commit(); \
    } while (0)

    ISSUE(0, 0); ISSUE(1, 1); ISSUE(2, 2); ISSUE(3, 3); ISSUE(4, 4);

    const int wm    = wid & 3;            // rows [wm*32, +32)
    const int wncol = (wid >> 2) * 64;    // cols [wncol, +64)
    const int g  = lane >> 2;
    const int tg = lane & 3;

    float c[2][8][4];
    #pragma unroll
    for (int m2 = 0; m2 < 2; m2++)
        #pragma unroll
        for (int nt = 0; nt < 8; nt++)
            #pragma unroll
            for (int j = 0; j < 4; j++) c[m2][nt][j] = 0.0f;

    for (int s = 0; s < NSLICE; s++) {
        const int st = s % NSTAGE;
        cp_wait();
        __syncthreads();

        const __half* As = sm->A[st];
        const __half* Ws = sm->W[st];
        #pragma unroll
        for (int kk = 0; kk < KSLICE; kk += 16) {
            uint32_t a[2][4];
            #pragma unroll
            for (int m2 = 0; m2 < 2; m2++) {
                const int r0 = (wm * 32 + m2 * 16 + g) * PIT + kk;
                a[m2][0] = *(const uint32_t*)(As + r0 + tg * 2);
                a[m2][1] = *(const uint32_t*)(As + r0 + 8 * PIT + tg * 2);
                a[m2][2] = *(const uint32_t*)(As + r0 + tg * 2 + 8);
                a[m2][3] = *(const uint32_t*)(As + r0 + 8 * PIT + tg * 2 + 8);
            }
            #pragma unroll
            for (int nt = 0; nt < 8; nt++) {
                const int ncol = wncol + nt * 8 + g;
                uint32_t b0 = *(const uint32_t*)(Ws + ncol * PIT + kk + tg * 2);
                uint32_t b1 = *(const uint32_t*)(Ws + ncol * PIT + kk + tg * 2 + 8);
                mma_f16(c[0][nt][0], c[0][nt][1], c[0][nt][2], c[0][nt][3],
                        a[0][0], a[0][1], a[0][2], a[0][3], b0, b1);
                mma_f16(c[1][nt][0], c[1][nt][1], c[1][nt][2], c[1][nt][3],
                        a[1][0], a[1][1], a[1][2], a[1][3], b0, b1);
            }
        }
        __syncthreads();
        if (s + NSTAGE < NSLICE) ISSUE(s + NSTAGE, st);
    }
    #undef ISSUE

    // ---- epilogue: rescale, bias via per-row true counts, relu, store ----
    #pragma unroll
    for (int m2 = 0; m2 < 2; m2++) {
        #pragma unroll
        for (int h = 0; h < 2; h++) {
            const int row = wm * 32 + m2 * 16 + h * 8 + g;
            const int d = base + row;
            if (d >= NNODES) continue;
            float cnt[NREL];
            #pragma unroll
            for (int r = 0; r < NREL; r++)
                cnt[r] = (float)g_counts[r * NNODES + d];
            #pragma unroll
            for (int nt = 0; nt < 8; nt++) {
                const int col0 = wncol + nt * 8 + tg * 2;
                float v0 = c[m2][nt][h * 2 + 0] * scale;
                float v1 = c[m2][nt][h * 2 + 1] * scale;
                #pragma unroll
                for (int r = 0; r < NREL; r++) {
                    const float cc = cnt[r];
                    v0 += cc * sm->bias[r * HID + col0];
                    v1 += cc * sm->bias[r * HID + col0 + 1];
                }
                if (relu) { v0 = fmaxf(v0, 0.f); v1 = fmaxf(v1, 0.f); }
                Hout[(size_t)d * HID + col0]     = v0;
                Hout[(size_t)d * HID + col0 + 1] = v1;
            }
        }
    }
}

// ---------------- launch ----------------------------------------------------
extern "C" void kernel_launch(void* const* d_in, const int* in_sizes, int n_in,
                              void* d_out, int out_size) {
    const int*   eidx  = (const int*)d_in[0];      // [2, NEDGES]: row0=dest, row1=src
    const int*   etype = (const int*)d_in[1];
    const float* emb   = (const float*)d_in[2];
    const float* wts   = (const float*)d_in[3];    // [3, NREL, HID, HID]
    const float* bias  = (const float*)d_in[4];    // [3, NREL, HID]
    float*       out   = (float*)d_out;

    const int* dest = eidx;
    const int* src  = eidx + NEDGES;

    float* hbuf = nullptr;
    cudaGetSymbolAddress((void**)&hbuf, g_H);
    float* H0 = hbuf;
    float* H1 = hbuf + (size_t)NNODES * HID;
    __half* wt = nullptr;
    cudaGetSymbolAddress((void**)&wt, g_Wh);
    __half* yb = nullptr;
    cudaGetSymbolAddress((void**)&yb, g_Y);

    k_init<<<(INITN + 255) / 256, 256>>>(wts);
    k_bucket<<<(NEDGES + 255) / 256, 256>>>(dest, etype, src);

    const int smem_sz = (int)sizeof(GSMem);
    static_assert(sizeof(GSMem) <= 113 * 1024, "gemm smem too big for 2 blocks/SM");
    cudaFuncSetAttribute(k_gemm, cudaFuncAttributeMaxDynamicSharedMemorySize, smem_sz);

    const size_t wstride = (size_t)NREL * HID * HID;
    const size_t bstride = (size_t)NREL * HID;
    dim3 ggrid(GRID_M, NREL);

    // Per-layer power-of-two Y scaling (exact): keeps fp16 in range.
    // layer1: A-sums <= 32                      -> s = 1
    // layer2: worst-bound A-sums ~ 5.4e4        -> s = 64
    // layer3: worst-bound A-sums ~ 7e8 (loose)  -> s = 16384
    const float S2 = 64.0f,  IS2 = 1.0f / 64.0f;
    const float S3 = 16384.0f, IS3 = 1.0f / 16384.0f;

    k_gather<<<ggrid, 256>>>(emb, 1.0f);
    k_gemm<<<GRID_M, 256, smem_sz>>>(yb, wt,               bias,               H0,  1, 1.0f);
    k_gather<<<ggrid, 256>>>(H0, IS2);
    k_gemm<<<GRID_M, 256, smem_sz>>>(yb, wt + wstride,     bias + bstride,     H1,  1, S2);
    k_gather<<<ggrid, 256>>>(H1, IS3);
    k_gemm<<<GRID_M, 256, smem_sz>>>(yb, wt + 2 * wstride, bias + 2 * bstride, out, 0, S3);
}

// round 14
// speedup vs baseline: 2.1330x; 1.1164x over previous
#include <cuda_runtime.h>
#include <cuda_fp16.h>
#include <cstdint>

#define NNODES  50000
#define HID     128
#define NREL    9
#define NEDGES  600000
#define RNBUCK  (NREL * NNODES)
#define CAP     32
#define WTOT    (3 * NREL * HID * HID)
#define INITN   ((RNBUCK > WTOT) ? RNBUCK : WTOT)   // cover BOTH ranges

#define MTILE   128
#define NROWPAD 50048                          // 391 * 128
#define GRID_M  (NROWPAD / MTILE)              // 391

#define NSTAGE  3
#define KSLICE  64
#define PIT     72                             // smem row pitch in halves (conflict-free for ldmatrix: 144B = +4 banks/row)
#define AS_ELE  (MTILE * PIT)                  // 9216 halves = 18432 B
#define AS_BYTES (AS_ELE * 2)
#define NSLICE  (NREL * 2)                     // 18 K-slices of 64

// ---------------- scratch (device globals; no allocation) ----------------
__device__ int    g_counts[RNBUCK];
__device__ int    g_bucket[(size_t)RNBUCK * CAP];                  // 57.6 MB
__device__ __align__(256) float  g_H[2][(size_t)NNODES * HID];
__device__ __align__(256) __half g_Wh[WTOT];                       // W^T fp16: [l][r][n][k]
__device__ __align__(256) __half g_Y[(size_t)NREL * NROWPAD * HID]; // 115 MB fp16

// ---------------- helpers ----------------
__device__ __forceinline__ void mma_f16(float& c0, float& c1, float& c2, float& c3,
                                        uint32_t a0, uint32_t a1, uint32_t a2, uint32_t a3,
                                        uint32_t b0, uint32_t b1) {
    asm volatile(
        "mma.sync.aligned.m16n8k16.row.col.f32.f16.f16.f32 "
        "{%0,%1,%2,%3}, {%4,%5,%6,%7}, {%8,%9}, {%0,%1,%2,%3};\n"
        : "+f"(c0), "+f"(c1), "+f"(c2), "+f"(c3)
        : "r"(a0), "r"(a1), "r"(a2), "r"(a3), "r"(b0), "r"(b1));
}
__device__ __forceinline__ void ldm_x4(uint32_t* r, uint32_t addr) {
    asm volatile("ldmatrix.sync.aligned.m8n8.x4.shared.b16 {%0,%1,%2,%3}, [%4];"
                 : "=r"(r[0]), "=r"(r[1]), "=r"(r[2]), "=r"(r[3]) : "r"(addr));
}
__device__ __forceinline__ void cp16(uint32_t sdst, const void* gsrc) {
    asm volatile("cp.async.cg.shared.global [%0], [%1], 16;\n"
                 :: "r"(sdst), "l"(gsrc) : "memory");
}
__device__ __forceinline__ void cp_commit() {
    asm volatile("cp.async.commit_group;\n" ::: "memory");
}
__device__ __forceinline__ void cp_wait() {      // NSTAGE-1 = 2
    asm volatile("cp.async.wait_group 2;\n" ::: "memory");
}

// ---------------- init: zero counts + fp16-transpose W ----------------
// g_Wh[(l*9+r)*16384 + n*128 + k] = (half) W[(l*9+r)*16384 + k*128 + n]
__global__ void k_init(const float* __restrict__ W) {
    int i = blockIdx.x * blockDim.x + threadIdx.x;
    if (i < WTOT) {
        int mat = i >> 14, within = i & 16383;
        int n = within >> 7, k = within & 127;
        g_Wh[i] = __float2half_rn(W[(mat << 14) + k * HID + n]);
    }
    if (i < RNBUCK) g_counts[i] = 0;
}

// ---------------- bucket scatter ----------------
__global__ void k_bucket(const int* __restrict__ dest, const int* __restrict__ etype,
                         const int* __restrict__ src) {
    int e = blockIdx.x * blockDim.x + threadIdx.x;
    if (e < NEDGES) {
        int key = etype[e] * NNODES + dest[e];
        int pos = atomicAdd(&g_counts[key], 1);
        if (pos < CAP) g_bucket[(size_t)key * CAP + pos] = src[e];
    }
}

// ---------------- gather: Y[r][n][:] = (half)( inv_s * sum_{src} Hin[src] ) -
// grid (391, 9), 256 threads. Each warp owns 16 dest rows of one relation.
__global__ void __launch_bounds__(256)
k_gather(const float* __restrict__ Hin, float inv_s) {
    const int lane = threadIdx.x & 31;
    const int wid  = threadIdx.x >> 5;
    const int r    = blockIdx.y;
    const int d0   = blockIdx.x * MTILE + wid * 16;
    const int mycol = lane * 4;                   // halves/floats index
    __half* Yg = g_Y + (size_t)r * NROWPAD * HID;

    int cnt = 0;
    {
        int dd = d0 + lane;
        if (lane < 16 && dd < NNODES) {
            cnt = g_counts[r * NNODES + dd];
            if (cnt > CAP) cnt = CAP;
        }
    }
    int x = cnt;
    #pragma unroll
    for (int o = 1; o < 32; o <<= 1) {
        int y = __shfl_up_sync(0xffffffffu, x, o);
        if (lane >= o) x += y;
    }
    const int excl  = x - cnt;
    const int total = __shfl_sync(0xffffffffu, excl, 16);

    float4 acc = make_float4(0.f, 0.f, 0.f, 0.f);
    int cur = 0;
    int nextb = __shfl_sync(0xffffffffu, excl, 1);

    #define FLUSH() do { \
        __half2 h0 = __floats2half2_rn(acc.x * inv_s, acc.y * inv_s); \
        __half2 h1 = __floats2half2_rn(acc.z * inv_s, acc.w * inv_s); \
        uint2 o_; o_.x = *(uint32_t*)&h0; o_.y = *(uint32_t*)&h1; \
        __stcs((uint2*)(Yg + (size_t)(d0 + cur) * HID + mycol), o_); \
        acc.x = acc.y = acc.z = acc.w = 0.f; \
        cur++; \
        int nb2 = __shfl_sync(0xffffffffu, excl, (cur < 16) ? (cur + 1) : 16); \
        nextb = (cur < 16) ? nb2 : 0x7fffffff; \
    } while (0)

    for (int ib = 0; ib < total; ib += 32) {
        int rem = total - ib; if (rem > 32) rem = 32;
        const int j = ib + lane;

        int row = -1;
        #pragma unroll
        for (int i = 0; i < 16; i++) {
            int p = __shfl_sync(0xffffffffu, excl, i);
            row += (p <= j) ? 1 : 0;
        }
        if (row < 0) row = 0;
        if (row > 15) row = 15;
        int rowExcl = __shfl_sync(0xffffffffu, excl, row);
        int slot = j - rowExcl;
        if (slot < 0) slot = 0;
        if (slot >= CAP) slot = CAP - 1;

        int sv = 0;
        if (lane < rem)
            sv = g_bucket[(size_t)(r * NNODES + d0 + row) * CAP + slot];

        int jj = 0;
        while (jj < rem) {
            int nb = rem - jj; if (nb > 8) nb = 8;
            float4 v[8];
            #pragma unroll
            for (int u = 0; u < 8; u++) {
                if (u < nb) {
                    int s = __shfl_sync(0xffffffffu, sv, jj + u);
                    v[u] = *(const float4*)(Hin + (size_t)s * HID + mycol);
                }
            }
            #pragma unroll
            for (int u = 0; u < 8; u++) {
                if (u < nb) {
                    int idx = ib + jj + u;
                    while (idx >= nextb) FLUSH();
                    acc.x += v[u].x; acc.y += v[u].y;
                    acc.z += v[u].z; acc.w += v[u].w;
                }
            }
            jj += nb;
        }
    }
    while (cur < 16) FLUSH();
    #undef FLUSH
}

// ---------------- GEMM: Hout = relu( s * sum_r Y_r @ W_r + cnt_r * b_r ) ----
// fp16 m16n8k16, fp32 accum, ldmatrix fragment loads.
// 3-stage cp.async pipeline, K-slice 64, 256 thr, 128x128 tile.
struct GSMem {
    __half A[NSTAGE][AS_ELE];    // 3 x 18 KB   [row 0..127][k 0..63] pitch 72
    __half W[NSTAGE][AS_ELE];    // 3 x 18 KB   [n 0..127][k 0..63]  pitch 72
    float bias[NREL * HID];      // 4.5 KB
};

__global__ void __launch_bounds__(256, 2)
k_gemm(const __half* __restrict__ Y, const __half* __restrict__ Wt_l,
       const float* __restrict__ Bv, float* __restrict__ Hout, int relu,
       float scale) {
    extern __shared__ __align__(16) char smraw[];
    GSMem* sm = (GSMem*)smraw;

    const int tid  = threadIdx.x;
    const int lane = tid & 31;
    const int wid  = tid >> 5;
    const int base = blockIdx.x * MTILE;

    for (int i = tid; i < NREL * HID; i += 256) sm->bias[i] = Bv[i];

    const uint32_t sA0 = (uint32_t)__cvta_generic_to_shared(&sm->A[0][0]);
    const uint32_t sW0 = (uint32_t)__cvta_generic_to_shared(&sm->W[0][0]);

    // issue K-slice s into stage st: 128 rows x 64 halves (128B = 8 cp16) each
    #define ISSUE(s_, st_) do { \
        const int r_  = (s_) >> 1; \
        const int ks_ = (s_) & 1; \
        const __half* Ag = Y + ((size_t)r_ * NROWPAD + base) * HID + ks_ * KSLICE; \
        const __half* Wg = Wt_l + ((size_t)r_ << 14) + ks_ * KSLICE; \
        const uint32_t sa = sA0 + (st_) * AS_BYTES; \
        const uint32_t sw = sW0 + (st_) * AS_BYTES; \
        _Pragma("unroll") \
        for (int u = 0; u < 4; u++) { \
            int j = tid + 256 * u; \
            int row = j >> 3, seg = j & 7; \
            cp16(sa + (row * PIT + seg * 8) * 2, Ag + (size_t)row * HID + seg * 8); \
            cp16(sw + (row * PIT + seg * 8) * 2, Wg + (size_t)row * HID + seg * 8); \
        } \
        cp_commit(); \
    } while (0)

    ISSUE(0, 0); ISSUE(1, 1); ISSUE(2, 2);

    const int wm    = wid & 3;            // rows [wm*32, +32)
    const int wncol = (wid >> 2) * 64;    // cols [wncol, +64)

    // ldmatrix per-lane source rows (verified against the scalar-frag mapping):
    // A x4 groups: {m0-7,k0-7},{m8-15,k0-7},{m0-7,k8-15},{m8-15,k8-15}
    const int rowA = wm * 32 + (lane & 7) + ((lane >> 3) & 1) * 8;   // + m2*16
    const int kA   = (lane >> 4) * 8;
    // B x4 groups: {n0-7,k0-7},{n0-7,k8-15},{n8-15,k0-7},{n8-15,k8-15}
    const int rowB = wncol + (lane & 7) + ((lane >> 4) & 1) * 8;     // + ntp*16
    const int kB   = ((lane >> 3) & 1) * 8;

    float c[2][8][4];
    #pragma unroll
    for (int m2 = 0; m2 < 2; m2++)
        #pragma unroll
        for (int nt = 0; nt < 8; nt++)
            #pragma unroll
            for (int j = 0; j < 4; j++) c[m2][nt][j] = 0.0f;

    for (int s = 0; s < NSLICE; s++) {
        const int st = s % NSTAGE;
        cp_wait();
        __syncthreads();

        const uint32_t aBase = sA0 + st * AS_BYTES + (rowA * PIT + kA) * 2;
        const uint32_t wBase = sW0 + st * AS_BYTES + (rowB * PIT + kB) * 2;

        #pragma unroll
        for (int kk = 0; kk < KSLICE; kk += 16) {
            uint32_t a[2][4];
            ldm_x4(a[0], aBase + kk * 2);
            ldm_x4(a[1], aBase + (16 * PIT + kk) * 2);
            #pragma unroll
            for (int ntp = 0; ntp < 4; ntp++) {
                uint32_t b[4];
                ldm_x4(b, wBase + (ntp * 16 * PIT + kk) * 2);
                const int nt0 = ntp * 2;
                mma_f16(c[0][nt0][0], c[0][nt0][1], c[0][nt0][2], c[0][nt0][3],
                        a[0][0], a[0][1], a[0][2], a[0][3], b[0], b[1]);
                mma_f16(c[1][nt0][0], c[1][nt0][1], c[1][nt0][2], c[1][nt0][3],
                        a[1][0], a[1][1], a[1][2], a[1][3], b[0], b[1]);
                mma_f16(c[0][nt0+1][0], c[0][nt0+1][1], c[0][nt0+1][2], c[0][nt0+1][3],
                        a[0][0], a[0][1], a[0][2], a[0][3], b[2], b[3]);
                mma_f16(c[1][nt0+1][0], c[1][nt0+1][1], c[1][nt0+1][2], c[1][nt0+1][3],
                        a[1][0], a[1][1], a[1][2], a[1][3], b[2], b[3]);
            }
        }
        __syncthreads();
        if (s + NSTAGE < NSLICE) ISSUE(s + NSTAGE, st);
    }
    #undef ISSUE

    // ---- epilogue: rescale, bias via per-row true counts, relu, store ----
    const int g  = lane >> 2;
    const int tg = lane & 3;
    #pragma unroll
    for (int m2 = 0; m2 < 2; m2++) {
        #pragma unroll
        for (int h = 0; h < 2; h++) {
            const int row = wm * 32 + m2 * 16 + h * 8 + g;
            const int d = base + row;
            if (d >= NNODES) continue;
            float cnt[NREL];
            #pragma unroll
            for (int r = 0; r < NREL; r++)
                cnt[r] = (float)g_counts[r * NNODES + d];
            #pragma unroll
            for (int nt = 0; nt < 8; nt++) {
                const int col0 = wncol + nt * 8 + tg * 2;
                float v0 = c[m2][nt][h * 2 + 0] * scale;
                float v1 = c[m2][nt][h * 2 + 1] * scale;
                #pragma unroll
                for (int r = 0; r < NREL; r++) {
                    const float cc = cnt[r];
                    v0 += cc * sm->bias[r * HID + col0];
                    v1 += cc * sm->bias[r * HID + col0 + 1];
                }
                if (relu) { v0 = fmaxf(v0, 0.f); v1 = fmaxf(v1, 0.f); }
                Hout[(size_t)d * HID + col0]     = v0;
                Hout[(size_t)d * HID + col0 + 1] = v1;
            }
        }
    }
}

// ---------------- launch ----------------------------------------------------
extern "C" void kernel_launch(void* const* d_in, const int* in_sizes, int n_in,
                              void* d_out, int out_size) {
    const int*   eidx  = (const int*)d_in[0];      // [2, NEDGES]: row0=dest, row1=src
    const int*   etype = (const int*)d_in[1];
    const float* emb   = (const float*)d_in[2];
    const float* wts   = (const float*)d_in[3];    // [3, NREL, HID, HID]
    const float* bias  = (const float*)d_in[4];    // [3, NREL, HID]
    float*       out   = (float*)d_out;

    const int* dest = eidx;
    const int* src  = eidx + NEDGES;

    float* hbuf = nullptr;
    cudaGetSymbolAddress((void**)&hbuf, g_H);
    float* H0 = hbuf;
    float* H1 = hbuf + (size_t)NNODES * HID;
    __half* wt = nullptr;
    cudaGetSymbolAddress((void**)&wt, g_Wh);
    __half* yb = nullptr;
    cudaGetSymbolAddress((void**)&yb, g_Y);

    k_init<<<(INITN + 255) / 256, 256>>>(wts);
    k_bucket<<<(NEDGES + 255) / 256, 256>>>(dest, etype, src);

    const int smem_sz = (int)sizeof(GSMem);
    static_assert(sizeof(GSMem) <= 113 * 1024, "gemm smem too big for 2 blocks/SM");
    cudaFuncSetAttribute(k_gemm, cudaFuncAttributeMaxDynamicSharedMemorySize, smem_sz);

    const size_t wstride = (size_t)NREL * HID * HID;
    const size_t bstride = (size_t)NREL * HID;
    dim3 ggrid(GRID_M, NREL);

    // Per-layer power-of-two Y scaling (exact): keeps fp16 in range.
    const float S2 = 64.0f,    IS2 = 1.0f / 64.0f;
    const float S3 = 16384.0f, IS3 = 1.0f / 16384.0f;

    k_gather<<<ggrid, 256>>>(emb, 1.0f);
    k_gemm<<<GRID_M, 256, smem_sz>>>(yb, wt,               bias,               H0,  1, 1.0f);
    k_gather<<<ggrid, 256>>>(H0, IS2);
    k_gemm<<<GRID_M, 256, smem_sz>>>(yb, wt + wstride,     bias + bstride,     H1,  1, S2);
    k_gather<<<ggrid, 256>>>(H1, IS3);
    k_gemm<<<GRID_M, 256, smem_sz>>>(yb, wt + 2 * wstride, bias + 2 * bstride, out, 0, S3);
}

// round 15
// speedup vs baseline: 2.3438x; 1.0988x over previous
#include <cuda_runtime.h>
#include <cuda_fp16.h>
#include <cstdint>

#define NNODES  50000
#define HID     128
#define NREL    9
#define NEDGES  600000
#define RNBUCK  (NREL * NNODES)
#define CAP     32
#define WTOT    (3 * NREL * HID * HID)
#define HTOT    (NNODES * HID)                 // 6.4M
#define INITN   HTOT                           // covers WTOT and RNBUCK too

#define MTILE   128
#define NROWPAD 50048                          // 391 * 128
#define GRID_M  (NROWPAD / MTILE)              // 391

#define NSTAGE  3
#define KSLICE  64
#define PIT     72                             // smem row pitch in halves
#define AS_ELE  (MTILE * PIT)
#define AS_BYTES (AS_ELE * 2)
#define NSLICE  (NREL * 2)                     // 18 K-slices of 64

// ---------------- scratch (device globals; no allocation) ----------------
__device__ int    g_counts[RNBUCK];
__device__ int    g_bucket[(size_t)RNBUCK * CAP];                  // 57.6 MB
__device__ __align__(256) __half g_Hh[3][HTOT];                    // fp16 emb/H1/H2
__device__ __align__(256) __half g_Wh[WTOT];                       // W^T fp16: [l][r][n][k]
__device__ __align__(256) __half g_Y[(size_t)NREL * NROWPAD * HID]; // 115 MB fp16

// ---------------- helpers ----------------
__device__ __forceinline__ void mma_f16(float& c0, float& c1, float& c2, float& c3,
                                        uint32_t a0, uint32_t a1, uint32_t a2, uint32_t a3,
                                        uint32_t b0, uint32_t b1) {
    asm volatile(
        "mma.sync.aligned.m16n8k16.row.col.f32.f16.f16.f32 "
        "{%0,%1,%2,%3}, {%4,%5,%6,%7}, {%8,%9}, {%0,%1,%2,%3};\n"
        : "+f"(c0), "+f"(c1), "+f"(c2), "+f"(c3)
        : "r"(a0), "r"(a1), "r"(a2), "r"(a3), "r"(b0), "r"(b1));
}
__device__ __forceinline__ void ldm_x4(uint32_t* r, uint32_t addr) {
    asm volatile("ldmatrix.sync.aligned.m8n8.x4.shared.b16 {%0,%1,%2,%3}, [%4];"
                 : "=r"(r[0]), "=r"(r[1]), "=r"(r[2]), "=r"(r[3]) : "r"(addr));
}
__device__ __forceinline__ void cp16(uint32_t sdst, const void* gsrc) {
    asm volatile("cp.async.cg.shared.global [%0], [%1], 16;\n"
                 :: "r"(sdst), "l"(gsrc) : "memory");
}
__device__ __forceinline__ void cp_commit() {
    asm volatile("cp.async.commit_group;\n" ::: "memory");
}
__device__ __forceinline__ void cp_wait() {      // NSTAGE-1 = 2
    asm volatile("cp.async.wait_group 2;\n" ::: "memory");
}

// ---------------- init: zero counts + fp16 W^T + fp16 emb ----------------
__global__ void k_init(const float* __restrict__ W, const float* __restrict__ emb) {
    int i = blockIdx.x * blockDim.x + threadIdx.x;
    if (i < WTOT) {
        int mat = i >> 14, within = i & 16383;
        int n = within >> 7, k = within & 127;
        g_Wh[i] = __float2half_rn(W[(mat << 14) + k * HID + n]);
    }
    if (i < RNBUCK) g_counts[i] = 0;
    if (i < HTOT)   g_Hh[0][i] = __float2half_rn(emb[i]);
}

// ---------------- bucket scatter ----------------
__global__ void k_bucket(const int* __restrict__ dest, const int* __restrict__ etype,
                         const int* __restrict__ src) {
    int e = blockIdx.x * blockDim.x + threadIdx.x;
    if (e < NEDGES) {
        int key = etype[e] * NNODES + dest[e];
        int pos = atomicAdd(&g_counts[key], 1);
        if (pos < CAP) g_bucket[(size_t)key * CAP + pos] = src[e];
    }
}

// ---------------- gather: Y[r][n][:] = (half)( inv_s * sum_{src} Hh[src] ) --
// grid (391, 9), 256 threads. Each warp owns 16 dest rows of one relation.
__global__ void __launch_bounds__(256)
k_gather(const __half* __restrict__ Hin, float inv_s) {
    const int lane = threadIdx.x & 31;
    const int wid  = threadIdx.x >> 5;
    const int r    = blockIdx.y;
    const int d0   = blockIdx.x * MTILE + wid * 16;
    const int mycol = lane * 4;                   // halves index
    __half* Yg = g_Y + (size_t)r * NROWPAD * HID;

    int cnt = 0;
    {
        int dd = d0 + lane;
        if (lane < 16 && dd < NNODES) {
            cnt = g_counts[r * NNODES + dd];
            if (cnt > CAP) cnt = CAP;
        }
    }
    int x = cnt;
    #pragma unroll
    for (int o = 1; o < 32; o <<= 1) {
        int y = __shfl_up_sync(0xffffffffu, x, o);
        if (lane >= o) x += y;
    }
    const int excl  = x - cnt;
    const int total = __shfl_sync(0xffffffffu, excl, 16);

    float4 acc = make_float4(0.f, 0.f, 0.f, 0.f);
    int cur = 0;
    int nextb = __shfl_sync(0xffffffffu, excl, 1);

    #define FLUSH() do { \
        __half2 h0 = __floats2half2_rn(acc.x * inv_s, acc.y * inv_s); \
        __half2 h1 = __floats2half2_rn(acc.z * inv_s, acc.w * inv_s); \
        uint2 o_; o_.x = *(uint32_t*)&h0; o_.y = *(uint32_t*)&h1; \
        __stcs((uint2*)(Yg + (size_t)(d0 + cur) * HID + mycol), o_); \
        acc.x = acc.y = acc.z = acc.w = 0.f; \
        cur++; \
        int nb2 = __shfl_sync(0xffffffffu, excl, (cur < 16) ? (cur + 1) : 16); \
        nextb = (cur < 16) ? nb2 : 0x7fffffff; \
    } while (0)

    for (int ib = 0; ib < total; ib += 32) {
        int rem = total - ib; if (rem > 32) rem = 32;
        const int j = ib + lane;

        int row = -1;
        #pragma unroll
        for (int i = 0; i < 16; i++) {
            int p = __shfl_sync(0xffffffffu, excl, i);
            row += (p <= j) ? 1 : 0;
        }
        if (row < 0) row = 0;
        if (row > 15) row = 15;
        int rowExcl = __shfl_sync(0xffffffffu, excl, row);
        int slot = j - rowExcl;
        if (slot < 0) slot = 0;
        if (slot >= CAP) slot = CAP - 1;

        int sv = 0;
        if (lane < rem)
            sv = g_bucket[(size_t)(r * NNODES + d0 + row) * CAP + slot];

        int jj = 0;
        while (jj < rem) {
            int nb = rem - jj; if (nb > 8) nb = 8;
            uint2 v[8];
            #pragma unroll
            for (int u = 0; u < 8; u++) {
                if (u < nb) {
                    int s = __shfl_sync(0xffffffffu, sv, jj + u);
                    v[u] = *(const uint2*)(Hin + (size_t)s * HID + mycol);
                }
            }
            #pragma unroll
            for (int u = 0; u < 8; u++) {
                if (u < nb) {
                    int idx = ib + jj + u;
                    while (idx >= nextb) FLUSH();
                    float2 f0 = __half22float2(*(__half2*)&v[u].x);
                    float2 f1 = __half22float2(*(__half2*)&v[u].y);
                    acc.x += f0.x; acc.y += f0.y;
                    acc.z += f1.x; acc.w += f1.y;
                }
            }
            jj += nb;
        }
    }
    while (cur < 16) FLUSH();
    #undef FLUSH
}

// ---------------- GEMM: H = relu( s * sum_r Y_r @ W_r + cnt_r * b_r ) -------
// fp16 m16n8k16, fp32 accum, ldmatrix fragment loads, 3-stage cp.async.
// Output: fp16 (scaled by out_inv) when HoutH != null, else fp32 to HoutF.
struct GSMem {
    __half A[NSTAGE][AS_ELE];
    __half W[NSTAGE][AS_ELE];
    float bias[NREL * HID];
};

__global__ void __launch_bounds__(256, 2)
k_gemm(const __half* __restrict__ Y, const __half* __restrict__ Wt_l,
       const float* __restrict__ Bv, float* __restrict__ HoutF,
       __half* __restrict__ HoutH, int relu, float scale, float out_inv) {
    extern __shared__ __align__(16) char smraw[];
    GSMem* sm = (GSMem*)smraw;

    const int tid  = threadIdx.x;
    const int lane = tid & 31;
    const int wid  = tid >> 5;
    const int base = blockIdx.x * MTILE;

    for (int i = tid; i < NREL * HID; i += 256) sm->bias[i] = Bv[i];

    const uint32_t sA0 = (uint32_t)__cvta_generic_to_shared(&sm->A[0][0]);
    const uint32_t sW0 = (uint32_t)__cvta_generic_to_shared(&sm->W[0][0]);

    #define ISSUE(s_, st_) do { \
        const int r_  = (s_) >> 1; \
        const int ks_ = (s_) & 1; \
        const __half* Ag = Y + ((size_t)r_ * NROWPAD + base) * HID + ks_ * KSLICE; \
        const __half* Wg = Wt_l + ((size_t)r_ << 14) + ks_ * KSLICE; \
        const uint32_t sa = sA0 + (st_) * AS_BYTES; \
        const uint32_t sw = sW0 + (st_) * AS_BYTES; \
        _Pragma("unroll") \
        for (int u = 0; u < 4; u++) { \
            int j = tid + 256 * u; \
            int row = j >> 3, seg = j & 7; \
            cp16(sa + (row * PIT + seg * 8) * 2, Ag + (size_t)row * HID + seg * 8); \
            cp16(sw + (row * PIT + seg * 8) * 2, Wg + (size_t)row * HID + seg * 8); \
        } \
        cp_commit(); \
    } while (0)

    ISSUE(0, 0); ISSUE(1, 1); ISSUE(2, 2);

    const int wm    = wid & 3;
    const int wncol = (wid >> 2) * 64;

    const int rowA = wm * 32 + (lane & 7) + ((lane >> 3) & 1) * 8;
    const int kA   = (lane >> 4) * 8;
    const int rowB = wncol + (lane & 7) + ((lane >> 4) & 1) * 8;
    const int kB   = ((lane >> 3) & 1) * 8;

    float c[2][8][4];
    #pragma unroll
    for (int m2 = 0; m2 < 2; m2++)
        #pragma unroll
        for (int nt = 0; nt < 8; nt++)
            #pragma unroll
            for (int j = 0; j < 4; j++) c[m2][nt][j] = 0.0f;

    for (int s = 0; s < NSLICE; s++) {
        const int st = s % NSTAGE;
        cp_wait();
        __syncthreads();

        const uint32_t aBase = sA0 + st * AS_BYTES + (rowA * PIT + kA) * 2;
        const uint32_t wBase = sW0 + st * AS_BYTES + (rowB * PIT + kB) * 2;

        #pragma unroll
        for (int kk = 0; kk < KSLICE; kk += 16) {
            uint32_t a[2][4];
            ldm_x4(a[0], aBase + kk * 2);
            ldm_x4(a[1], aBase + (16 * PIT + kk) * 2);
            #pragma unroll
            for (int ntp = 0; ntp < 4; ntp++) {
                uint32_t b[4];
                ldm_x4(b, wBase + (ntp * 16 * PIT + kk) * 2);
                const int nt0 = ntp * 2;
                mma_f16(c[0][nt0][0], c[0][nt0][1], c[0][nt0][2], c[0][nt0][3],
                        a[0][0], a[0][1], a[0][2], a[0][3], b[0], b[1]);
                mma_f16(c[1][nt0][0], c[1][nt0][1], c[1][nt0][2], c[1][nt0][3],
                        a[1][0], a[1][1], a[1][2], a[1][3], b[0], b[1]);
                mma_f16(c[0][nt0+1][0], c[0][nt0+1][1], c[0][nt0+1][2], c[0][nt0+1][3],
                        a[0][0], a[0][1], a[0][2], a[0][3], b[2], b[3]);
                mma_f16(c[1][nt0+1][0], c[1][nt0+1][1], c[1][nt0+1][2], c[1][nt0+1][3],
                        a[1][0], a[1][1], a[1][2], a[1][3], b[2], b[3]);
            }
        }
        __syncthreads();
        if (s + NSTAGE < NSLICE) ISSUE(s + NSTAGE, st);
    }
    #undef ISSUE

    // ---- epilogue: rescale, bias via per-row true counts, relu, store ----
    const int g  = lane >> 2;
    const int tg = lane & 3;
    #pragma unroll
    for (int m2 = 0; m2 < 2; m2++) {
        #pragma unroll
        for (int h = 0; h < 2; h++) {
            const int row = wm * 32 + m2 * 16 + h * 8 + g;
            const int d = base + row;
            if (d >= NNODES) continue;
            float cnt[NREL];
            #pragma unroll
            for (int r = 0; r < NREL; r++)
                cnt[r] = (float)g_counts[r * NNODES + d];
            #pragma unroll
            for (int nt = 0; nt < 8; nt++) {
                const int col0 = wncol + nt * 8 + tg * 2;
                float v0 = c[m2][nt][h * 2 + 0] * scale;
                float v1 = c[m2][nt][h * 2 + 1] * scale;
                #pragma unroll
                for (int r = 0; r < NREL; r++) {
                    const float cc = cnt[r];
                    v0 += cc * sm->bias[r * HID + col0];
                    v1 += cc * sm->bias[r * HID + col0 + 1];
                }
                if (relu) { v0 = fmaxf(v0, 0.f); v1 = fmaxf(v1, 0.f); }
                if (HoutH) {
                    __half2 p = __floats2half2_rn(v0 * out_inv, v1 * out_inv);
                    *(__half2*)(HoutH + (size_t)d * HID + col0) = p;
                } else {
                    HoutF[(size_t)d * HID + col0]     = v0;
                    HoutF[(size_t)d * HID + col0 + 1] = v1;
                }
            }
        }
    }
}

// ---------------- launch ----------------------------------------------------
extern "C" void kernel_launch(void* const* d_in, const int* in_sizes, int n_in,
                              void* d_out, int out_size) {
    const int*   eidx  = (const int*)d_in[0];      // [2, NEDGES]: row0=dest, row1=src
    const int*   etype = (const int*)d_in[1];
    const float* emb   = (const float*)d_in[2];
    const float* wts   = (const float*)d_in[3];    // [3, NREL, HID, HID]
    const float* bias  = (const float*)d_in[4];    // [3, NREL, HID]
    float*       out   = (float*)d_out;

    const int* dest = eidx;
    const int* src  = eidx + NEDGES;

    __half* hh = nullptr;
    cudaGetSymbolAddress((void**)&hh, g_Hh);
    __half* hh0 = hh;                      // fp16 emb
    __half* hh1 = hh + (size_t)HTOT;       // H1          (scale 1)
    __half* hh2 = hh + (size_t)2 * HTOT;   // H2 * 2^-11
    __half* wt = nullptr;
    cudaGetSymbolAddress((void**)&wt, g_Wh);
    __half* yb = nullptr;
    cudaGetSymbolAddress((void**)&yb, g_Y);

    k_init<<<(INITN + 255) / 256, 256>>>(wts, emb);
    k_bucket<<<(NEDGES + 255) / 256, 256>>>(dest, etype, src);

    const int smem_sz = (int)sizeof(GSMem);
    static_assert(sizeof(GSMem) <= 113 * 1024, "gemm smem too big for 2 blocks/SM");
    cudaFuncSetAttribute(k_gemm, cudaFuncAttributeMaxDynamicSharedMemorySize, smem_sz);

    const size_t wstride = (size_t)NREL * HID * HID;
    const size_t bstride = (size_t)NREL * HID;
    dim3 ggrid(GRID_M, NREL);

    // Exact power-of-2 scaling chain (fp16 range safety, worst-case bounds):
    //  L1: Y1 = A1 (<=32*1)            gemm*1      -> H1 fp16 (<=844)
    //  L2: Y2 = A2 * 2^-6 (<=422)      gemm*2^6    -> H2*2^-11 fp16 (<=3e4 bound)
    //  L3: Y3 = A3 * 2^-11 * 2^-5      gemm*2^16   -> fp32 out
    k_gather<<<ggrid, 256>>>(hh0, 1.0f);
    k_gemm<<<GRID_M, 256, smem_sz>>>(yb, wt, bias, nullptr, hh1, 1,
                                     1.0f, 1.0f);
    k_gather<<<ggrid, 256>>>(hh1, 1.0f / 64.0f);
    k_gemm<<<GRID_M, 256, smem_sz>>>(yb, wt + wstride, bias + bstride, nullptr, hh2, 1,
                                     64.0f, 1.0f / 2048.0f);
    k_gather<<<ggrid, 256>>>(hh2, 1.0f / 32.0f);
    k_gemm<<<GRID_M, 256, smem_sz>>>(yb, wt + 2 * wstride, bias + 2 * bstride, out, nullptr, 0,
                                     65536.0f, 1.0f);
}